// round 13
// baseline (speedup 1.0000x reference)
#include <cuda_runtime.h>

#define NB    32
#define NN    8192
#define NCLIP 256
#define CAPB  512           // padded per-batch array stride
#define MAXG  12            // max 32-col groups (cnt <= 384, 8-sigma margin)
#define MAXC  (32 * MAXG)   // 384
#define NBUCK 4096
#define FULL  0xffffffffu

// Scratch (__device__ globals; allocation-free rule).
// g_hist is zero-initialized at load and re-zeroed by K3 each call.
__device__ int      g_off[NB + 1];
__device__ float    g_ss[NN + CAPB];           // per-batch sorted starts (+pad)
__device__ float    g_se[NN + CAPB];           // per-batch sorted ends   (+pad)
__device__ float    g_ssc[NN];                 // sorted scores
__device__ int      g_sidx[NN];                // sorted slot -> original index
__device__ unsigned g_sup[NB * MAXG * CAPB];   // masks, w-major
__device__ int      g_hist[NBUCK];
__device__ int      g_list[NN];                // bucket-grouped original indices
__device__ int      g_rank[NN];                // global rank per original index

__device__ __forceinline__ int bucket_of(float s) {
    int b = (int)(s * (float)NBUCK);
    return b < 0 ? 0 : (b >= NBUCK ? NBUCK - 1 : b);
}

// ---------------------------------------------------------------------------
// K1: blocks 0..31 per-batch sort | 32..63 gt_dist | 64..95 histogram build
// ---------------------------------------------------------------------------
__global__ void k1_kernel(const float* __restrict__ gt,
                          const int*   __restrict__ bidx,
                          const float* __restrict__ pred,
                          const float* __restrict__ score,
                          float* __restrict__ out) {
    int blk = blockIdx.x;
    int tid = threadIdx.x;
    if (blk < NB) {                                    // ---- per-batch sort ----
        int b = blk;
        __shared__ int sob, soe;
        __shared__ float rsc[CAPB];
        if (tid == 0) {
            int lo = 0, hi = NN;
            while (lo < hi) { int m = (lo + hi) >> 1; if (bidx[m] < b) lo = m + 1; else hi = m; }
            int ob = lo;
            hi = NN;
            while (lo < hi) { int m = (lo + hi) >> 1; if (bidx[m] < b + 1) lo = m + 1; else hi = m; }
            sob = ob; soe = lo;
            g_off[b] = ob;
            if (b == NB - 1) g_off[NB] = NN;
        }
        __syncthreads();
        int ob  = sob;
        int cnt = soe - ob;
        if (cnt > MAXC) cnt = MAXC;
        for (int t = tid; t < cnt; t += 256) rsc[t] = score[ob + t];
        __syncthreads();
        for (int t = tid; t < cnt; t += 256) {
            float si = rsc[t];
            int wr = 0;
            for (int j = 0; j < cnt; j++) {
                float sj = rsc[j];
                wr += (sj > si) || (sj == si && j < t);
            }
            int i = ob + t;
            float2 p2 = ((const float2*)pred)[i];
            g_ss[ob + wr]   = p2.x;
            g_se[ob + wr]   = p2.y;
            g_ssc[ob + wr]  = si;
            g_sidx[ob + wr] = i;
        }
    } else if (blk < 2 * NB) {                         // ---- gt_dist ----
        int b = blk - NB, c = tid;
        float s = gt[2 * b];
        float e = gt[2 * b + 1];
        float len  = 256.0f * (e - s);
        float cen0 = 256.0f * s;
        float cen1 = 256.0f * e;
        float cen2 = 128.0f * (s + e);
        float sgS  = 0.25f * len;
        float sgM  = 0.21f * len;
        float inv2sS = 1.0f / (2.0f * sgS * sgS);
        float inv2sM = 1.0f / (2.0f * sgM * sgM);
        float fc = (float)c;
        float d0 = fc - cen0, d1 = fc - cen1, d2 = fc - cen2;
        float* o = out + ((size_t)b * NCLIP + c) * 3;
        o[0] = expf(-d0 * d0 * inv2sS);
        o[1] = expf(-d1 * d1 * inv2sS);
        o[2] = expf(-d2 * d2 * inv2sM);
    } else {                                           // ---- histogram ----
        int i = (blk - 2 * NB) * 256 + tid;
        atomicAdd(&g_hist[bucket_of(score[i])], 1);    // counts: deterministic
    }
}

// ---------------------------------------------------------------------------
// K2: blocks 0..383 mask build | block 384: hist scan + bucket lists + ranks
// ---------------------------------------------------------------------------
__global__ void k2_kernel(const float* __restrict__ score) {
    int blk = blockIdx.x;
    int tid = threadIdx.x;

    if (blk < MAXG * NB) {
        // ---- mask build: CTA per (group g, batch b) ----
        int g = blk % MAXG;
        int b = blk / MAXG;
        int ob  = g_off[b];
        int cnt = g_off[b + 1] - ob;
        if (cnt > MAXC) cnt = MAXC;
        if (32 * g >= cnt) return;

        __shared__ float ss[MAXC], se_[MAXC], sl[MAXC];
        int rows = 32 * (g + 1);
        for (int i = tid; i < rows; i += 256) {
            float s = g_ss[ob + i], e = g_se[ob + i];   // pad makes OOB-safe
            ss[i] = s; se_[i] = e; sl[i] = e - s;
        }
        __syncthreads();

        int jl = tid & 31;
        int wh = tid >> 5;
        int j  = 32 * g + jl;
        if (j >= cnt) return;
        float sj = ss[j], ej = se_[j], lj = sl[j];
        for (int w = wh; w <= g; w += 8) {
            unsigned word = 0;
            int rb = 32 * w;
#pragma unroll
            for (int k = 0; k < 32; k++) {
                float si_ = ss[rb + k], ei_ = se_[rb + k], li_ = sl[rb + k];
                float interc = fmaxf(fminf(ej, ei_) - fmaxf(sj, si_), 0.0f);
                float uni = lj + li_ - interc;
                float um  = fmaxf(uni, 1e-8f);
                float diff = interc - 0.5f * um;
                bool sp;
                if (fabsf(diff) <= 1e-6f * um) sp = (interc / um) > 0.5f;
                else                           sp = diff > 0.0f;
                if (sp) word |= 1u << k;
            }
            if (w == g) word &= (1u << jl) - 1u;
            g_sup[(b * MAXG + w) * CAPB + j] = word;
        }
        return;
    }

    // ---- scan + bucket lists + per-element ranks (single CTA) ----
    __shared__ int spfx[NBUCK + 1];   // exclusive prefix (kept in smem)
    __shared__ int scur[NBUCK];       // bucket cursors
    __shared__ int spart[256];
    for (int k = tid; k < NBUCK; k += 256) spfx[k] = g_hist[k];
    __syncthreads();

    int base_t = tid * 16;
    int local[16];
    {
        int sum = 0;
#pragma unroll
        for (int k = 0; k < 16; k++) { local[k] = sum; sum += spfx[base_t + k]; }
        spart[tid] = sum;
    }
    __syncthreads();
    if (tid < 32) {
        int vals[8], v = 0;
#pragma unroll
        for (int q = 0; q < 8; q++) { vals[q] = spart[tid * 8 + q]; v += vals[q]; }
        int inc = v;
#pragma unroll
        for (int ofs = 1; ofs < 32; ofs <<= 1) {
            int n = __shfl_up_sync(FULL, inc, ofs);
            if (tid >= ofs) inc += n;
        }
        int run = inc - v;
#pragma unroll
        for (int q = 0; q < 8; q++) { spart[tid * 8 + q] = run; run += vals[q]; }
    }
    __syncthreads();
    {
        int base = spart[tid];
        int p[16];
#pragma unroll
        for (int k = 0; k < 16; k++) p[k] = base + local[k];
        __syncthreads();              // all spfx reads done before overwrite
#pragma unroll
        for (int k = 0; k < 16; k++) { spfx[base_t + k] = p[k]; scur[base_t + k] = p[k]; }
        if (tid == 255) spfx[NBUCK] = NN;
    }
    __syncthreads();
    for (int i = tid; i < NN; i += 256) {
        int pos = atomicAdd(&scur[bucket_of(score[i])], 1);
        g_list[pos] = i;              // list order nondeterministic; use is not
    }
    __syncthreads();                  // g_list visible block-wide

    // Per-element global rank (independent, L1-resident scores)
    for (int m = tid; m < NN; m += 256) {
        int   i  = g_list[m];
        float si = score[i];
        int bk = bucket_of(si);
        int lo = spfx[bk], hi = spfx[bk + 1];
        int r  = NN - hi;                        // strictly higher buckets
        for (int q = lo; q < hi; q++) {          // same bucket: exact tie-break
            int j = g_list[q];
            float sj = score[j];
            r += (sj > si) || (sj == si && j < i);
        }
        g_rank[i] = r;
    }
}

// ---------------------------------------------------------------------------
// K3: per-batch — vectorized mask prefetch + ballot-fixpoint scan +
// writeback (rank precomputed) + re-zero g_hist for next call.
// ---------------------------------------------------------------------------
__global__ void k3_kernel(float* __restrict__ out) {
    __shared__ __align__(16) unsigned ssup[MAXG * MAXC];   // 18 KB
    __shared__ unsigned skeep[MAXG];
    int b   = blockIdx.x;
    int tid = threadIdx.x;

    // re-zero histogram for the next kernel_launch call (no deps in this kernel)
    {
        int k = b * 256 + tid;
        if (k < NBUCK) g_hist[k] = 0;
    }

    int ob  = g_off[b];
    int cnt = g_off[b + 1] - ob;
    if (cnt > MAXC) cnt = MAXC;
    if (cnt == 0) return;
    int nG = (cnt + 31) >> 5;

    // Coalesced uint4 prefetch of this batch's mask words
    int nwv = (32 * nG) >> 2;                    // uint4s per word-row
    for (int w = 0; w < nG; w++) {
        const uint4* src = (const uint4*)&g_sup[(b * MAXG + w) * CAPB];
        uint4*       dst = (uint4*)&ssup[w * MAXC];
        for (int j = tid; j < nwv; j += 256) dst[j] = src[j];
    }
    __syncthreads();

    // Ballot-fixpoint greedy scan (warp 0, SMEM masks)
    if (tid < 32) {
        int lane = tid;
        for (int g = 0; g < nG; g++) {
            int j = 32 * g + lane;
            bool valid = j < cnt;
            unsigned dead = 0;
            for (int w = 0; w < g; w++)
                dead |= valid ? (ssup[w * MAXC + j] & skeep[w]) : 0u;
            unsigned pend = valid ? ssup[g * MAXC + j] : 0u;
            bool alive0 = valid && (dead == 0u);
            unsigned M = __ballot_sync(FULL, alive0);
            for (;;) {                           // unique fixpoint = greedy
                unsigned Mn = __ballot_sync(FULL, alive0 && ((pend & M) == 0u));
                if (Mn == M) break;
                M = Mn;
            }
            skeep[g] = M;
            __syncwarp();
        }
    }
    __syncthreads();

    // Writeback at global sorted positions (all loads independent)
    float* obds = out + (size_t)NB * NCLIP * 3;
    float* osc  = obds + 2 * NN;
    for (int t = tid; t < cnt; t += 256) {
        int r = g_rank[g_sidx[ob + t]];
        float f = ((skeep[t >> 5] >> (t & 31)) & 1u) ? 1.0f : 0.0f;
        obds[2 * r]     = g_ss[ob + t] * f;
        obds[2 * r + 1] = g_se[ob + t] * f;
        osc[r]          = g_ssc[ob + t] * f;
    }
}

// ---------------------------------------------------------------------------
extern "C" void kernel_launch(void* const* d_in, const int* in_sizes, int n_in,
                              void* d_out, int out_size) {
    const float* gt    = (const float*)d_in[0];
    const float* pred  = (const float*)d_in[1];
    const float* score = (const float*)d_in[2];
    const int*   bidx  = (const int*)d_in[3];
    float* out = (float*)d_out;

    k1_kernel<<<3 * NB, 256>>>(gt, bidx, pred, score, out);
    k2_kernel<<<MAXG * NB + 1, 256>>>(score);
    k3_kernel<<<NB, 256>>>(out);
}

// round 14
// speedup vs baseline: 2.1988x; 2.1988x over previous
#include <cuda_runtime.h>

#define NB    32
#define NN    8192
#define NCLIP 256
#define CAPB  512           // padded per-batch array stride
#define MAXG  12            // max 32-col groups (cnt <= 384, 8-sigma margin)
#define MAXC  (32 * MAXG)   // 384
#define NBUCK 4096
#define QC    6             // sort CTAs per batch
#define EPC   64            // elements per sort CTA
#define FULL  0xffffffffu

// Scratch (__device__ globals; allocation-free rule)
__device__ int      g_off[NB + 1];
__device__ float    g_ss[NN + CAPB];           // per-batch sorted starts (+pad)
__device__ float    g_se[NN + CAPB];           // per-batch sorted ends   (+pad)
__device__ float    g_ssc[NN];                 // sorted scores
__device__ int      g_sidx[NN];                // sorted slot -> original index
__device__ unsigned g_sup[NB * MAXG * CAPB];   // masks, w-major
__device__ int      g_pfx[NBUCK + 1];          // exclusive bucket prefix
__device__ int      g_list[NN];                // bucket-grouped original indices
__device__ int      g_rank[NN];                // global rank per original index

__device__ __forceinline__ int bucket_of(float s) {
    int b = (int)(s * 4096.0f);                // *2^12 is exact
    return b < 0 ? 0 : (b >= NBUCK ? NBUCK - 1 : b);
}

// ---------------------------------------------------------------------------
// K1: blocks 0..191 chunked per-batch sort | 192..223 gt_dist |
//     block 224: smem histogram + prefix + bucket lists
// ---------------------------------------------------------------------------
__global__ void k1_kernel(const float* __restrict__ gt,
                          const int*   __restrict__ bidx,
                          const float* __restrict__ pred,
                          const float* __restrict__ score,
                          float* __restrict__ out) {
    int blk = blockIdx.x;
    int tid = threadIdx.x;

    if (blk < NB * QC) {                       // ---- chunked per-batch sort ----
        int b = blk / QC, q = blk % QC;
        __shared__ int sob, soe;
        __shared__ float rsc[MAXC];
        __shared__ int spar[256];
        if (tid == 0) {
            int lo = 0, hi = NN;
            while (lo < hi) { int m = (lo + hi) >> 1; if (bidx[m] < b) lo = m + 1; else hi = m; }
            int ob = lo;
            hi = NN;
            while (lo < hi) { int m = (lo + hi) >> 1; if (bidx[m] < b + 1) lo = m + 1; else hi = m; }
            sob = ob; soe = lo;
            if (q == 0) {
                g_off[b] = ob;
                if (b == NB - 1) g_off[NB] = NN;
            }
        }
        __syncthreads();
        int ob  = sob;
        int cnt = soe - ob;
        if (cnt > MAXC) cnt = MAXC;
        for (int t = tid; t < cnt; t += 256) rsc[t] = score[ob + t];
        __syncthreads();

        int e = tid & 63;                      // element lane
        int c = tid >> 6;                      // chunk 0..3 (warp-uniform)
        int t = q * EPC + e;
        int chunk = (cnt + 3) >> 2;
        int cl = c * chunk;
        int cu = cl + chunk; if (cu > cnt) cu = cnt;
        int part = 0;
        if (t < cnt) {
            float si = rsc[t];
            for (int j = cl; j < cu; j++) {
                float sj = rsc[j];
                part += (sj > si) || (sj == si && j < t);
            }
        }
        spar[tid] = part;
        __syncthreads();
        if (c == 0 && t < cnt) {
            int wr = spar[e] + spar[64 + e] + spar[128 + e] + spar[192 + e];
            int i = ob + t;
            float2 p2 = ((const float2*)pred)[i];
            g_ss[ob + wr]   = p2.x;
            g_se[ob + wr]   = p2.y;
            g_ssc[ob + wr]  = rsc[t];
            g_sidx[ob + wr] = i;
        }
        return;
    }

    if (blk < NB * QC + NB) {                  // ---- gt_dist ----
        int b = blk - NB * QC, c = tid;
        float s = gt[2 * b];
        float e = gt[2 * b + 1];
        float len  = 256.0f * (e - s);
        float cen0 = 256.0f * s;
        float cen1 = 256.0f * e;
        float cen2 = 128.0f * (s + e);
        float sgS  = 0.25f * len;
        float sgM  = 0.21f * len;
        float inv2sS = 1.0f / (2.0f * sgS * sgS);
        float inv2sM = 1.0f / (2.0f * sgM * sgM);
        float fc = (float)c;
        float d0 = fc - cen0, d1 = fc - cen1, d2 = fc - cen2;
        float* o = out + ((size_t)b * NCLIP + c) * 3;
        o[0] = expf(-d0 * d0 * inv2sS);
        o[1] = expf(-d1 * d1 * inv2sS);
        o[2] = expf(-d2 * d2 * inv2sM);
        return;
    }

    // ---- single CTA: smem histogram + prefix + bucket lists ----
    {
        __shared__ int sh[NBUCK];
        __shared__ int scur[NBUCK];
        __shared__ int sps[256];
        for (int k = tid; k < NBUCK; k += 256) sh[k] = 0;
        __syncthreads();
        for (int i = tid; i < NN; i += 256)
            atomicAdd(&sh[bucket_of(score[i])], 1);      // counts: deterministic
        __syncthreads();

        int base_t = tid * 16;
        int local[16];
        {
            int sum = 0;
#pragma unroll
            for (int k = 0; k < 16; k++) { local[k] = sum; sum += sh[base_t + k]; }
            sps[tid] = sum;
        }
        __syncthreads();
        if (tid < 32) {
            int vals[8], v = 0;
#pragma unroll
            for (int q = 0; q < 8; q++) { vals[q] = sps[tid * 8 + q]; v += vals[q]; }
            int inc = v;
#pragma unroll
            for (int ofs = 1; ofs < 32; ofs <<= 1) {
                int n = __shfl_up_sync(FULL, inc, ofs);
                if (tid >= ofs) inc += n;
            }
            int run = inc - v;
#pragma unroll
            for (int q = 0; q < 8; q++) { sps[tid * 8 + q] = run; run += vals[q]; }
        }
        __syncthreads();
        {
            int base = sps[tid];
#pragma unroll
            for (int k = 0; k < 16; k++) {
                int p = base + local[k];
                g_pfx[base_t + k] = p;
                scur[base_t + k]  = p;
            }
            if (tid == 255) g_pfx[NBUCK] = NN;
        }
        __syncthreads();
        for (int i = tid; i < NN; i += 256) {
            int pos = atomicAdd(&scur[bucket_of(score[i])], 1);
            g_list[pos] = i;           // list order nondeterministic; use is not
        }
    }
}

// ---------------------------------------------------------------------------
// K2: blocks 0..383 mask build | blocks 384..415 wide rank finalize
// ---------------------------------------------------------------------------
__global__ void k2_kernel(const float* __restrict__ score) {
    int blk = blockIdx.x;
    int tid = threadIdx.x;

    if (blk < MAXG * NB) {
        // ---- mask build: CTA per (group g, batch b) ----
        int g = blk % MAXG;
        int b = blk / MAXG;
        int ob  = g_off[b];
        int cnt = g_off[b + 1] - ob;
        if (cnt > MAXC) cnt = MAXC;
        if (32 * g >= cnt) return;

        __shared__ float ss[MAXC], se_[MAXC], sl[MAXC];
        int rows = 32 * (g + 1);
        for (int i = tid; i < rows; i += 256) {
            float s = g_ss[ob + i], e = g_se[ob + i];   // pad makes OOB-safe
            ss[i] = s; se_[i] = e; sl[i] = e - s;
        }
        __syncthreads();

        int jl = tid & 31;
        int wh = tid >> 5;
        int j  = 32 * g + jl;
        if (j >= cnt) return;
        float sj = ss[j], ej = se_[j], lj = sl[j];
        for (int w = wh; w <= g; w += 8) {
            unsigned word = 0;
            int rb = 32 * w;
#pragma unroll
            for (int k = 0; k < 32; k++) {
                float si_ = ss[rb + k], ei_ = se_[rb + k], li_ = sl[rb + k];
                float interc = fmaxf(fminf(ej, ei_) - fmaxf(sj, si_), 0.0f);
                float uni = lj + li_ - interc;
                float um  = fmaxf(uni, 1e-8f);
                float diff = interc - 0.5f * um;
                bool sp;
                if (fabsf(diff) <= 1e-6f * um) sp = (interc / um) > 0.5f;
                else                           sp = diff > 0.0f;
                if (sp) word |= 1u << k;
            }
            if (w == g) word &= (1u << jl) - 1u;
            g_sup[(b * MAXG + w) * CAPB + j] = word;
        }
        return;
    }

    // ---- wide rank finalize: 1 element per thread, coalesced ----
    int i  = (blk - MAXG * NB) * 256 + tid;
    float si = score[i];
    int bk = bucket_of(si);
    int lo = g_pfx[bk], hi = g_pfx[bk + 1];
    int r  = NN - hi;                          // strictly higher buckets
    for (int m = lo; m < hi; m++) {            // same bucket: exact tie-break
        int j = g_list[m];
        float sj = score[j];
        r += (sj > si) || (sj == si && j < i);
    }
    g_rank[i] = r;
}

// ---------------------------------------------------------------------------
// K3: per-batch — vectorized mask prefetch + ballot-fixpoint scan + writeback
// ---------------------------------------------------------------------------
__global__ void k3_kernel(float* __restrict__ out) {
    __shared__ __align__(16) unsigned ssup[MAXG * MAXC];   // 18 KB
    __shared__ unsigned skeep[MAXG];
    int b   = blockIdx.x;
    int tid = threadIdx.x;
    int ob  = g_off[b];
    int cnt = g_off[b + 1] - ob;
    if (cnt > MAXC) cnt = MAXC;
    if (cnt == 0) return;
    int nG = (cnt + 31) >> 5;

    // Coalesced uint4 prefetch of this batch's mask words
    int nwv = (32 * nG) >> 2;
    for (int w = 0; w < nG; w++) {
        const uint4* src = (const uint4*)&g_sup[(b * MAXG + w) * CAPB];
        uint4*       dst = (uint4*)&ssup[w * MAXC];
        for (int j = tid; j < nwv; j += 256) dst[j] = src[j];
    }
    __syncthreads();

    // Ballot-fixpoint greedy scan (warp 0, SMEM masks)
    if (tid < 32) {
        int lane = tid;
        for (int g = 0; g < nG; g++) {
            int j = 32 * g + lane;
            bool valid = j < cnt;
            unsigned dead = 0;
            for (int w = 0; w < g; w++)
                dead |= valid ? (ssup[w * MAXC + j] & skeep[w]) : 0u;
            unsigned pend = valid ? ssup[g * MAXC + j] : 0u;
            bool alive0 = valid && (dead == 0u);
            unsigned M = __ballot_sync(FULL, alive0);
            for (;;) {                         // unique fixpoint = greedy
                unsigned Mn = __ballot_sync(FULL, alive0 && ((pend & M) == 0u));
                if (Mn == M) break;
                M = Mn;
            }
            skeep[g] = M;
            __syncwarp();
        }
    }
    __syncthreads();

    // Writeback at global sorted positions (independent loads)
    float* obds = out + (size_t)NB * NCLIP * 3;
    float* osc  = obds + 2 * NN;
    for (int t = tid; t < cnt; t += 256) {
        int r = g_rank[g_sidx[ob + t]];
        float f = ((skeep[t >> 5] >> (t & 31)) & 1u) ? 1.0f : 0.0f;
        obds[2 * r]     = g_ss[ob + t] * f;
        obds[2 * r + 1] = g_se[ob + t] * f;
        osc[r]          = g_ssc[ob + t] * f;
    }
}

// ---------------------------------------------------------------------------
extern "C" void kernel_launch(void* const* d_in, const int* in_sizes, int n_in,
                              void* d_out, int out_size) {
    const float* gt    = (const float*)d_in[0];
    const float* pred  = (const float*)d_in[1];
    const float* score = (const float*)d_in[2];
    const int*   bidx  = (const int*)d_in[3];
    float* out = (float*)d_out;

    k1_kernel<<<NB * QC + NB + 1, 256>>>(gt, bidx, pred, score, out);
    k2_kernel<<<MAXG * NB + NN / 256, 256>>>(score);
    k3_kernel<<<NB, 256>>>(out);
}

// round 15
// speedup vs baseline: 2.2769x; 1.0356x over previous
#include <cuda_runtime.h>

#define NB    32
#define NN    8192
#define NCLIP 256
#define CAPB  512           // padded per-batch array stride
#define MAXG  12            // max 32-col groups (cnt <= 384, 8-sigma margin)
#define MAXC  (32 * MAXG)   // 384
#define NBUCK 4096
#define QC    6             // sort CTAs per batch
#define EPC   64            // elements per sort CTA
#define FULL  0xffffffffu

// Scratch (__device__ globals; allocation-free rule)
__device__ int      g_off[NB + 1];
__device__ float    g_ss[NN + CAPB];           // per-batch sorted starts (+pad)
__device__ float    g_se[NN + CAPB];           // per-batch sorted ends   (+pad)
__device__ float    g_ssc[NN];                 // sorted scores
__device__ int      g_sidx[NN];                // sorted slot -> original index
__device__ unsigned g_sup[NB * MAXG * CAPB];   // masks, w-major
__device__ int      g_pfx[NBUCK + 1];          // exclusive bucket prefix
__device__ int      g_list[NN];                // bucket-grouped original indices
__device__ int      g_rank[NN];                // global rank per original index

__device__ __forceinline__ int bucket_of(float s) {
    int b = (int)(s * 4096.0f);                // *2^12 is exact
    return b < 0 ? 0 : (b >= NBUCK ? NBUCK - 1 : b);
}

// ---------------------------------------------------------------------------
// K1: blocks 0..191 chunked per-batch sort | 192..223 gt_dist |
//     block 224: smem histogram + prefix + bucket lists
// ---------------------------------------------------------------------------
__global__ void k1_kernel(const float* __restrict__ gt,
                          const int*   __restrict__ bidx,
                          const float* __restrict__ pred,
                          const float* __restrict__ score,
                          float* __restrict__ out) {
    int blk = blockIdx.x;
    int tid = threadIdx.x;

    if (blk < NB * QC) {                       // ---- chunked per-batch sort ----
        int b = blk / QC, q = blk % QC;
        __shared__ int scnt[2][8];
        __shared__ int sobse[2];
        __shared__ float rsc[MAXC];
        __shared__ int spar[256];

        // Cooperative offset count: ob=#{bidx<b}, oe=#{bidx<b+1}. Wide + MLP.
        {
            int c0 = 0, c1 = 0;
            const int4* b4 = (const int4*)bidx;
            for (int t = tid; t < NN / 4; t += 256) {
                int4 v = b4[t];
                c0 += (v.x < b) + (v.y < b) + (v.z < b) + (v.w < b);
                c1 += (v.x <= b) + (v.y <= b) + (v.z <= b) + (v.w <= b);
            }
#pragma unroll
            for (int o = 16; o; o >>= 1) {
                c0 += __shfl_down_sync(FULL, c0, o);
                c1 += __shfl_down_sync(FULL, c1, o);
            }
            if ((tid & 31) == 0) { scnt[0][tid >> 5] = c0; scnt[1][tid >> 5] = c1; }
            __syncthreads();
            if (tid < 2) {
                int s = 0;
#pragma unroll
                for (int w = 0; w < 8; w++) s += scnt[tid][w];
                sobse[tid] = s;
                if (q == 0 && tid == 0) {
                    g_off[b] = s;                       // ob
                    if (b == NB - 1) g_off[NB] = NN;
                }
            }
            __syncthreads();
        }
        int ob  = sobse[0];
        int cnt = sobse[1] - ob;
        if (cnt > MAXC) cnt = MAXC;
        for (int t = tid; t < cnt; t += 256) rsc[t] = score[ob + t];
        __syncthreads();

        int e = tid & 63;                      // element lane
        int c = tid >> 6;                      // chunk 0..3 (warp-uniform)
        int t = q * EPC + e;
        int chunk = (cnt + 3) >> 2;
        int cl = c * chunk;
        int cu = cl + chunk; if (cu > cnt) cu = cnt;
        int part = 0;
        if (t < cnt) {
            float si = rsc[t];
            for (int j = cl; j < cu; j++) {
                float sj = rsc[j];
                part += (sj > si) || (sj == si && j < t);
            }
        }
        spar[tid] = part;
        __syncthreads();
        if (c == 0 && t < cnt) {
            int wr = spar[e] + spar[64 + e] + spar[128 + e] + spar[192 + e];
            int i = ob + t;
            float2 p2 = ((const float2*)pred)[i];
            g_ss[ob + wr]   = p2.x;
            g_se[ob + wr]   = p2.y;
            g_ssc[ob + wr]  = rsc[t];
            g_sidx[ob + wr] = i;
        }
        return;
    }

    if (blk < NB * QC + NB) {                  // ---- gt_dist ----
        int b = blk - NB * QC, c = tid;
        float s = gt[2 * b];
        float e = gt[2 * b + 1];
        float len  = 256.0f * (e - s);
        float cen0 = 256.0f * s;
        float cen1 = 256.0f * e;
        float cen2 = 128.0f * (s + e);
        float sgS  = 0.25f * len;
        float sgM  = 0.21f * len;
        float inv2sS = 1.0f / (2.0f * sgS * sgS);
        float inv2sM = 1.0f / (2.0f * sgM * sgM);
        float fc = (float)c;
        float d0 = fc - cen0, d1 = fc - cen1, d2 = fc - cen2;
        float* o = out + ((size_t)b * NCLIP + c) * 3;
        o[0] = expf(-d0 * d0 * inv2sS);
        o[1] = expf(-d1 * d1 * inv2sS);
        o[2] = expf(-d2 * d2 * inv2sM);
        return;
    }

    // ---- single CTA: smem histogram + prefix + bucket lists ----
    {
        __shared__ int sh[NBUCK];
        __shared__ int scur[NBUCK];
        __shared__ int sps[256];
        for (int k = tid; k < NBUCK; k += 256) sh[k] = 0;
        __syncthreads();
        for (int i = tid; i < NN; i += 256)
            atomicAdd(&sh[bucket_of(score[i])], 1);      // counts: deterministic
        __syncthreads();

        int base_t = tid * 16;
        int local[16];
        {
            int sum = 0;
#pragma unroll
            for (int k = 0; k < 16; k++) { local[k] = sum; sum += sh[base_t + k]; }
            sps[tid] = sum;
        }
        __syncthreads();
        if (tid < 32) {
            int vals[8], v = 0;
#pragma unroll
            for (int q = 0; q < 8; q++) { vals[q] = sps[tid * 8 + q]; v += vals[q]; }
            int inc = v;
#pragma unroll
            for (int ofs = 1; ofs < 32; ofs <<= 1) {
                int n = __shfl_up_sync(FULL, inc, ofs);
                if (tid >= ofs) inc += n;
            }
            int run = inc - v;
#pragma unroll
            for (int q = 0; q < 8; q++) { sps[tid * 8 + q] = run; run += vals[q]; }
        }
        __syncthreads();
        {
            int base = sps[tid];
#pragma unroll
            for (int k = 0; k < 16; k++) {
                int p = base + local[k];
                g_pfx[base_t + k] = p;
                scur[base_t + k]  = p;
            }
            if (tid == 255) g_pfx[NBUCK] = NN;
        }
        __syncthreads();
        for (int i = tid; i < NN; i += 256) {
            int pos = atomicAdd(&scur[bucket_of(score[i])], 1);
            g_list[pos] = i;           // list order nondeterministic; use is not
        }
    }
}

// ---------------------------------------------------------------------------
// K2: blocks 0..383 mask build | blocks 384..415 wide rank finalize
// ---------------------------------------------------------------------------
__global__ void k2_kernel(const float* __restrict__ score) {
    int blk = blockIdx.x;
    int tid = threadIdx.x;

    if (blk < MAXG * NB) {
        // ---- mask build: CTA per (group g, batch b) ----
        int g = blk % MAXG;
        int b = blk / MAXG;
        int ob  = g_off[b];
        int cnt = g_off[b + 1] - ob;
        if (cnt > MAXC) cnt = MAXC;
        if (32 * g >= cnt) return;

        __shared__ float ss[MAXC], se_[MAXC], sl[MAXC];
        int rows = 32 * (g + 1);
        for (int i = tid; i < rows; i += 256) {
            float s = g_ss[ob + i], e = g_se[ob + i];   // pad makes OOB-safe
            ss[i] = s; se_[i] = e; sl[i] = e - s;
        }
        __syncthreads();

        int jl = tid & 31;
        int wh = tid >> 5;
        int j  = 32 * g + jl;
        if (j >= cnt) return;
        float sj = ss[j], ej = se_[j], lj = sl[j];
        for (int w = wh; w <= g; w += 8) {
            unsigned word = 0;
            int rb = 32 * w;
#pragma unroll
            for (int k = 0; k < 32; k++) {
                float si_ = ss[rb + k], ei_ = se_[rb + k], li_ = sl[rb + k];
                float interc = fmaxf(fminf(ej, ei_) - fmaxf(sj, si_), 0.0f);
                float uni = lj + li_ - interc;
                float um  = fmaxf(uni, 1e-8f);
                float diff = interc - 0.5f * um;
                bool sp;
                if (fabsf(diff) <= 1e-6f * um) sp = (interc / um) > 0.5f;
                else                           sp = diff > 0.0f;
                if (sp) word |= 1u << k;
            }
            if (w == g) word &= (1u << jl) - 1u;
            g_sup[(b * MAXG + w) * CAPB + j] = word;
        }
        return;
    }

    // ---- wide rank finalize: 1 element per thread, coalesced ----
    int i  = (blk - MAXG * NB) * 256 + tid;
    float si = score[i];
    int bk = bucket_of(si);
    int lo = g_pfx[bk], hi = g_pfx[bk + 1];
    int r  = NN - hi;                          // strictly higher buckets
    for (int m = lo; m < hi; m++) {            // same bucket: exact tie-break
        int j = g_list[m];
        float sj = score[j];
        r += (sj > si) || (sj == si && j < i);
    }
    g_rank[i] = r;
}

// ---------------------------------------------------------------------------
// K3: per-batch — vectorized mask prefetch + ballot-fixpoint scan + writeback
// ---------------------------------------------------------------------------
__global__ void k3_kernel(float* __restrict__ out) {
    __shared__ __align__(16) unsigned ssup[MAXG * MAXC];   // 18 KB
    __shared__ unsigned skeep[MAXG];
    int b   = blockIdx.x;
    int tid = threadIdx.x;
    int ob  = g_off[b];
    int cnt = g_off[b + 1] - ob;
    if (cnt > MAXC) cnt = MAXC;
    if (cnt == 0) return;
    int nG = (cnt + 31) >> 5;

    // Coalesced uint4 prefetch of this batch's mask words
    int nwv = (32 * nG) >> 2;
    for (int w = 0; w < nG; w++) {
        const uint4* src = (const uint4*)&g_sup[(b * MAXG + w) * CAPB];
        uint4*       dst = (uint4*)&ssup[w * MAXC];
        for (int j = tid; j < nwv; j += 256) dst[j] = src[j];
    }
    __syncthreads();

    // Ballot-fixpoint greedy scan (warp 0, SMEM masks)
    if (tid < 32) {
        int lane = tid;
        for (int g = 0; g < nG; g++) {
            int j = 32 * g + lane;
            bool valid = j < cnt;
            unsigned dead = 0;
            for (int w = 0; w < g; w++)
                dead |= valid ? (ssup[w * MAXC + j] & skeep[w]) : 0u;
            unsigned pend = valid ? ssup[g * MAXC + j] : 0u;
            bool alive0 = valid && (dead == 0u);
            unsigned M = __ballot_sync(FULL, alive0);
            for (;;) {                         // unique fixpoint = greedy
                unsigned Mn = __ballot_sync(FULL, alive0 && ((pend & M) == 0u));
                if (Mn == M) break;
                M = Mn;
            }
            skeep[g] = M;
            __syncwarp();
        }
    }
    __syncthreads();

    // Writeback at global sorted positions (independent loads)
    float* obds = out + (size_t)NB * NCLIP * 3;
    float* osc  = obds + 2 * NN;
    for (int t = tid; t < cnt; t += 256) {
        int r = g_rank[g_sidx[ob + t]];
        float f = ((skeep[t >> 5] >> (t & 31)) & 1u) ? 1.0f : 0.0f;
        obds[2 * r]     = g_ss[ob + t] * f;
        obds[2 * r + 1] = g_se[ob + t] * f;
        osc[r]          = g_ssc[ob + t] * f;
    }
}

// ---------------------------------------------------------------------------
extern "C" void kernel_launch(void* const* d_in, const int* in_sizes, int n_in,
                              void* d_out, int out_size) {
    const float* gt    = (const float*)d_in[0];
    const float* pred  = (const float*)d_in[1];
    const float* score = (const float*)d_in[2];
    const int*   bidx  = (const int*)d_in[3];
    float* out = (float*)d_out;

    k1_kernel<<<NB * QC + NB + 1, 256>>>(gt, bidx, pred, score, out);
    k2_kernel<<<MAXG * NB + NN / 256, 256>>>(score);
    k3_kernel<<<NB, 256>>>(out);
}

// round 16
// speedup vs baseline: 2.7477x; 1.2068x over previous
#include <cuda_runtime.h>

#define NB    32
#define NN    8192
#define NCLIP 256
#define CAPB  512
#define MAXG  12
#define MAXC  (32 * MAXG)
#define NBUCK 4096
#define BCAP  32
#define QC    6
#define EPC   64
#define FULL  0xffffffffu

__device__ int      g_off[NB + 1];
__device__ float    g_ss[NN + CAPB];
__device__ float    g_se[NN + CAPB];
__device__ float    g_ssc[NN];
__device__ int      g_sidx[NN];
__device__ unsigned g_sup[NB * MAXG * CAPB];
__device__ int      g_hist[NBUCK];
__device__ int      g_bucktab[NBUCK * BCAP];
__device__ int      g_rank[NN];

__device__ __forceinline__ int bucket_of(float s) {
    int b = (int)(s * 4096.0f);
    return b < 0 ? 0 : (b >= NBUCK ? NBUCK - 1 : b);
}

__global__ void k1_kernel(const float* __restrict__ gt,
                          const int*   __restrict__ bidx,
                          const float* __restrict__ pred,
                          const float* __restrict__ score,
                          float* __restrict__ out) {
    int blk = blockIdx.x;
    int tid = threadIdx.x;

    if (blk < NB * QC) {
        int b = blk / QC, q = blk % QC;
        __shared__ int scnt[2][8];
        __shared__ int sobse[2];
        __shared__ float rsc[MAXC];
        __shared__ int spar[256];
        {
            int c0 = 0, c1 = 0;
            const int4* b4 = (const int4*)bidx;
            for (int t = tid; t < NN / 4; t += 256) {
                int4 v = b4[t];
                c0 += (v.x < b) + (v.y < b) + (v.z < b) + (v.w < b);
                c1 += (v.x <= b) + (v.y <= b) + (v.z <= b) + (v.w <= b);
            }
#pragma unroll
            for (int o = 16; o; o >>= 1) {
                c0 += __shfl_down_sync(FULL, c0, o);
                c1 += __shfl_down_sync(FULL, c1, o);
            }
            if ((tid & 31) == 0) { scnt[0][tid >> 5] = c0; scnt[1][tid >> 5] = c1; }
            __syncthreads();
            if (tid < 2) {
                int s = 0;
#pragma unroll
                for (int w = 0; w < 8; w++) s += scnt[tid][w];
                sobse[tid] = s;
                if (q == 0 && tid == 0) {
                    g_off[b] = s;
                    if (b == NB - 1) g_off[NB] = NN;
                }
            }
            __syncthreads();
        }
        int ob  = sobse[0];
        int cnt = sobse[1] - ob;
        if (cnt > MAXC) cnt = MAXC;
        for (int t = tid; t < cnt; t += 256) rsc[t] = score[ob + t];
        __syncthreads();

        int e = tid & 63;
        int c = tid >> 6;
        int t = q * EPC + e;
        int chunk = (cnt + 3) >> 2;
        int cl = c * chunk;
        int cu = cl + chunk; if (cu > cnt) cu = cnt;
        int part = 0;
        if (t < cnt) {
            float si = rsc[t];
            for (int j = cl; j < cu; j++) {
                float sj = rsc[j];
                part += (sj > si) || (sj == si && j < t);
            }
        }
        spar[tid] = part;
        __syncthreads();
        if (c == 0 && t < cnt) {
            int wr = spar[e] + spar[64 + e] + spar[128 + e] + spar[192 + e];
            int i = ob + t;
            float2 p2 = ((const float2*)pred)[i];
            g_ss[ob + wr]   = p2.x;
            g_se[ob + wr]   = p2.y;
            g_ssc[ob + wr]  = rsc[t];
            g_sidx[ob + wr] = i;
        }
        return;
    }

    if (blk < NB * QC + NB) {
        int b = blk - NB * QC, c = tid;
        float s = gt[2 * b];
        float e = gt[2 * b + 1];
        float len  = 256.0f * (e - s);
        float cen0 = 256.0f * s;
        float cen1 = 256.0f * e;
        float cen2 = 128.0f * (s + e);
        float sgS  = 0.25f * len;
        float sgM  = 0.21f * len;
        float inv2sS = 1.0f / (2.0f * sgS * sgS);
        float inv2sM = 1.0f / (2.0f * sgM * sgM);
        float fc = (float)c;
        float d0 = fc - cen0, d1 = fc - cen1, d2 = fc - cen2;
        float* o = out + ((size_t)b * NCLIP + c) * 3;
        o[0] = expf(-d0 * d0 * inv2sS);
        o[1] = expf(-d1 * d1 * inv2sS);
        o[2] = expf(-d2 * d2 * inv2sM);
        return;
    }

    {   // wide hist + bucket table (32 blocks, 1 elem/thread)
        int i  = (blk - NB * QC - NB) * 256 + tid;
        int bk = bucket_of(score[i]);
        int pos = atomicAdd(&g_hist[bk], 1);
        if (pos < BCAP) g_bucktab[bk * BCAP + pos] = i;
    }
}

__global__ void k2_kernel(const float* __restrict__ score) {
    int blk = blockIdx.x;
    int tid = threadIdx.x;

    if (blk < MAXG * NB) {
        int g = blk % MAXG;
        int b = blk / MAXG;
        int ob  = g_off[b];
        int cnt = g_off[b + 1] - ob;
        if (cnt > MAXC) cnt = MAXC;
        if (32 * g >= cnt) return;

        __shared__ float ss[MAXC], se_[MAXC], sl[MAXC];
        int rows = 32 * (g + 1);
        for (int i = tid; i < rows; i += 256) {
            float s = g_ss[ob + i], e = g_se[ob + i];
            ss[i] = s; se_[i] = e; sl[i] = e - s;
        }
        __syncthreads();

        int jl = tid & 31;
        int wh = tid >> 5;
        int j  = 32 * g + jl;
        if (j >= cnt) return;
        float sj = ss[j], ej = se_[j], lj = sl[j];
        for (int w = wh; w <= g; w += 8) {
            unsigned word = 0;
            int rb = 32 * w;
#pragma unroll
            for (int k = 0; k < 32; k++) {
                float si_ = ss[rb + k], ei_ = se_[rb + k], li_ = sl[rb + k];
                float interc = fmaxf(fminf(ej, ei_) - fmaxf(sj, si_), 0.0f);
                float uni = lj + li_ - interc;
                float um  = fmaxf(uni, 1e-8f);
                float diff = interc - 0.5f * um;
                bool sp;
                if (fabsf(diff) <= 1e-6f * um) sp = (interc / um) > 0.5f;
                else                           sp = diff > 0.0f;
                if (sp) word |= 1u << k;
            }
            if (w == g) word &= (1u << jl) - 1u;
            g_sup[(b * MAXG + w) * CAPB + j] = word;
        }
        return;
    }

    {   // wide rank: per-CTA smem prefix of hist, then 1 elem/thread
        __shared__ int spfx[NBUCK + 1];
        __shared__ int sps[256];
        int base_t = tid * 16;
        int local[16];
        {
            const int4* h4 = (const int4*)g_hist;
            int sum = 0;
#pragma unroll
            for (int k4 = 0; k4 < 4; k4++) {
                int4 v = h4[tid * 4 + k4];
                local[k4 * 4 + 0] = sum; sum += v.x;
                local[k4 * 4 + 1] = sum; sum += v.y;
                local[k4 * 4 + 2] = sum; sum += v.z;
                local[k4 * 4 + 3] = sum; sum += v.w;
            }
            sps[tid] = sum;
        }
        __syncthreads();
        if (tid < 32) {
            int vals[8], v = 0;
#pragma unroll
            for (int q = 0; q < 8; q++) { vals[q] = sps[tid * 8 + q]; v += vals[q]; }
            int inc = v;
#pragma unroll
            for (int ofs = 1; ofs < 32; ofs <<= 1) {
                int n = __shfl_up_sync(FULL, inc, ofs);
                if (tid >= ofs) inc += n;
            }
            int run = inc - v;
#pragma unroll
            for (int q = 0; q < 8; q++) { sps[tid * 8 + q] = run; run += vals[q]; }
        }
        __syncthreads();
        {
            int base = sps[tid];
#pragma unroll
            for (int k = 0; k < 16; k++) spfx[base_t + k] = base + local[k];
            if (tid == 255) spfx[NBUCK] = NN;
        }
        __syncthreads();

        int i  = (blk - MAXG * NB) * 256 + tid;
        float si = score[i];
        int bk = bucket_of(si);
        int lo = spfx[bk], hi = spfx[bk + 1];
        int r  = NN - hi;
        int hcnt = hi - lo; if (hcnt > BCAP) hcnt = BCAP;
        for (int m = 0; m < hcnt; m++) {
            int j = g_bucktab[bk * BCAP + m];
            float sj = score[j];
            r += (sj > si) || (sj == si && j < i);
        }
        g_rank[i] = r;
    }
}

__global__ void k3_kernel(float* __restrict__ out) {
    __shared__ __align__(16) unsigned ssup[MAXG * MAXC];
    __shared__ unsigned skeep[MAXG];
    int b   = blockIdx.x;
    int tid = threadIdx.x;

    if (tid < 128) g_hist[b * 128 + tid] = 0;   // self-clean for next call

    int ob  = g_off[b];
    int cnt = g_off[b + 1] - ob;
    if (cnt > MAXC) cnt = MAXC;
    if (cnt == 0) return;
    int nG = (cnt + 31) >> 5;

    int nwv = (32 * nG) >> 2;
    for (int w = 0; w < nG; w++) {
        const uint4* src = (const uint4*)&g_sup[(b * MAXG + w) * CAPB];
        uint4*       dst = (uint4*)&ssup[w * MAXC];
        for (int j = tid; j < nwv; j += 256) dst[j] = src[j];
    }
    __syncthreads();

    if (tid < 32) {
        int lane = tid;
        for (int g = 0; g < nG; g++) {
            int j = 32 * g + lane;
            bool valid = j < cnt;
            unsigned dead = 0;
            for (int w = 0; w < g; w++)
                dead |= valid ? (ssup[w * MAXC + j] & skeep[w]) : 0u;
            unsigned pend = valid ? ssup[g * MAXC + j] : 0u;
            bool alive0 = valid && (dead == 0u);
            unsigned M = __ballot_sync(FULL, alive0);
            for (;;) {
                unsigned Mn = __ballot_sync(FULL, alive0 && ((pend & M) == 0u));
                if (Mn == M) break;
                M = Mn;
            }
            skeep[g] = M;
            __syncwarp();
        }
    }
    __syncthreads();

    float* obds = out + (size_t)NB * NCLIP * 3;
    float* osc  = obds + 2 * NN;
    for (int t = tid; t < cnt; t += 256) {
        int r = g_rank[g_sidx[ob + t]];
        float f = ((skeep[t >> 5] >> (t & 31)) & 1u) ? 1.0f : 0.0f;
        obds[2 * r]     = g_ss[ob + t] * f;
        obds[2 * r + 1] = g_se[ob + t] * f;
        osc[r]          = g_ssc[ob + t] * f;
    }
}

extern "C" void kernel_launch(void* const* d_in, const int* in_sizes, int n_in,
                              void* d_out, int out_size) {
    const float* gt    = (const float*)d_in[0];
    const float* pred  = (const float*)d_in[1];
    const float* score = (const float*)d_in[2];
    const int*   bidx  = (const int*)d_in[3];
    float* out = (float*)d_out;

    k1_kernel<<<NB * QC + NB + NN / 256, 256>>>(gt, bidx, pred, score, out);
    k2_kernel<<<MAXG * NB + NN / 256, 256>>>(score);
    k3_kernel<<<NB, 256>>>(out);
}

// round 17
// speedup vs baseline: 2.8593x; 1.0406x over previous
#include <cuda_runtime.h>

#define NB    32
#define NN    8192
#define NCLIP 256
#define CAPB  512
#define MAXG  12
#define MAXC  (32 * MAXG)
#define NBUCK 4096
#define BCAP  32
#define QC    12            // sort CTAs per batch
#define EPC   32            // elements per sort CTA
#define NCH   8             // compare chunks per element
#define FULL  0xffffffffu

__device__ int      g_off[NB + 1];
__device__ float    g_ss[NN + CAPB];
__device__ float    g_se[NN + CAPB];
__device__ float    g_ssc[NN];
__device__ int      g_sidx[NN];
__device__ unsigned g_sup[NB * MAXG * CAPB];
__device__ int      g_hist[NBUCK];
__device__ int      g_bucktab[NBUCK * BCAP];
__device__ int      g_rank[NN];

__device__ __forceinline__ int bucket_of(float s) {
    int b = (int)(s * 4096.0f);
    return b < 0 ? 0 : (b >= NBUCK ? NBUCK - 1 : b);
}

// ---------------------------------------------------------------------------
// K1: blocks 0..383 chunked per-batch sort | 384..415 gt_dist |
//     416..447 wide hist + bucket-table build
// ---------------------------------------------------------------------------
__global__ void k1_kernel(const float* __restrict__ gt,
                          const int*   __restrict__ bidx,
                          const float* __restrict__ pred,
                          const float* __restrict__ score,
                          float* __restrict__ out) {
    int blk = blockIdx.x;
    int tid = threadIdx.x;

    if (blk < NB * QC) {                       // ---- chunked per-batch sort ----
        int b = blk / QC, q = blk % QC;
        __shared__ int scnt[2][8];
        __shared__ int sobse[2];
        __shared__ __align__(16) float rsc[MAXC + 4];
        __shared__ int spar[256];

        // Cooperative offset count: ob=#{bidx<b}, oe=#{bidx<b+1}.
        {
            int c0 = 0, c1 = 0;
            const int4* b4 = (const int4*)bidx;
            for (int t = tid; t < NN / 4; t += 256) {
                int4 v = b4[t];
                c0 += (v.x < b) + (v.y < b) + (v.z < b) + (v.w < b);
                c1 += (v.x <= b) + (v.y <= b) + (v.z <= b) + (v.w <= b);
            }
#pragma unroll
            for (int o = 16; o; o >>= 1) {
                c0 += __shfl_down_sync(FULL, c0, o);
                c1 += __shfl_down_sync(FULL, c1, o);
            }
            if ((tid & 31) == 0) { scnt[0][tid >> 5] = c0; scnt[1][tid >> 5] = c1; }
            __syncthreads();
            if (tid < 2) {
                int s = 0;
#pragma unroll
                for (int w = 0; w < 8; w++) s += scnt[tid][w];
                sobse[tid] = s;
                if (q == 0 && tid == 0) {
                    g_off[b] = s;
                    if (b == NB - 1) g_off[NB] = NN;
                }
            }
            __syncthreads();
        }
        int ob  = sobse[0];
        int cnt = sobse[1] - ob;
        if (cnt > MAXC) cnt = MAXC;
        int cnt4 = (cnt + 3) & ~3;
        for (int t = tid; t < cnt4; t += 256)
            rsc[t] = (t < cnt) ? score[ob + t] : -1.0f;   // pad: compares false
        __syncthreads();

        int e = tid & 31;                      // element lane
        int c = tid >> 5;                      // chunk 0..7
        int t = q * EPC + e;
        int chunkv = (((cnt + NCH - 1) / NCH) + 3) & ~3;  // 16B-aligned chunks
        int cl = c * chunkv;
        int cu = cl + chunkv; if (cu > cnt4) cu = cnt4;
        int part = 0;
        if (t < cnt) {
            float si = rsc[t];
            for (int j4 = cl; j4 < cu; j4 += 4) {
                float4 v = *(const float4*)&rsc[j4];
                part += (v.x > si) || (v.x == si && (j4 + 0) < t);
                part += (v.y > si) || (v.y == si && (j4 + 1) < t);
                part += (v.z > si) || (v.z == si && (j4 + 2) < t);
                part += (v.w > si) || (v.w == si && (j4 + 3) < t);
            }
        }
        spar[tid] = part;
        __syncthreads();
        if (c == 0 && t < cnt) {
            int wr = 0;
#pragma unroll
            for (int cc = 0; cc < NCH; cc++) wr += spar[cc * 32 + e];
            int i = ob + t;
            float2 p2 = ((const float2*)pred)[i];
            g_ss[ob + wr]   = p2.x;
            g_se[ob + wr]   = p2.y;
            g_ssc[ob + wr]  = rsc[t];
            g_sidx[ob + wr] = i;
        }
        return;
    }

    if (blk < NB * QC + NB) {                  // ---- gt_dist ----
        int b = blk - NB * QC, c = tid;
        float s = gt[2 * b];
        float e = gt[2 * b + 1];
        float len  = 256.0f * (e - s);
        float cen0 = 256.0f * s;
        float cen1 = 256.0f * e;
        float cen2 = 128.0f * (s + e);
        float sgS  = 0.25f * len;
        float sgM  = 0.21f * len;
        float inv2sS = 1.0f / (2.0f * sgS * sgS);
        float inv2sM = 1.0f / (2.0f * sgM * sgM);
        float fc = (float)c;
        float d0 = fc - cen0, d1 = fc - cen1, d2 = fc - cen2;
        float* o = out + ((size_t)b * NCLIP + c) * 3;
        o[0] = expf(-d0 * d0 * inv2sS);
        o[1] = expf(-d1 * d1 * inv2sS);
        o[2] = expf(-d2 * d2 * inv2sM);
        return;
    }

    {   // ---- wide hist + bucket table (32 blocks, 1 elem/thread) ----
        int i  = (blk - NB * QC - NB) * 256 + tid;
        int bk = bucket_of(score[i]);
        int pos = atomicAdd(&g_hist[bk], 1);   // counts deterministic
        if (pos < BCAP) g_bucktab[bk * BCAP + pos] = i;   // order racy; use is order-independent
    }
}

// ---------------------------------------------------------------------------
// K2: blocks 0..383 mask build | blocks 384..415 wide rank
// ---------------------------------------------------------------------------
__global__ void k2_kernel(const float* __restrict__ score) {
    int blk = blockIdx.x;
    int tid = threadIdx.x;

    if (blk < MAXG * NB) {
        int g = blk % MAXG;
        int b = blk / MAXG;
        int ob  = g_off[b];
        int cnt = g_off[b + 1] - ob;
        if (cnt > MAXC) cnt = MAXC;
        if (32 * g >= cnt) return;

        __shared__ float ss[MAXC], se_[MAXC], sl[MAXC];
        int rows = 32 * (g + 1);
        for (int i = tid; i < rows; i += 256) {
            float s = g_ss[ob + i], e = g_se[ob + i];   // pad makes OOB-safe
            ss[i] = s; se_[i] = e; sl[i] = e - s;
        }
        __syncthreads();

        int jl = tid & 31;
        int wh = tid >> 5;
        int j  = 32 * g + jl;
        if (j >= cnt) return;
        float sj = ss[j], ej = se_[j], lj = sl[j];
        for (int w = wh; w <= g; w += 8) {
            unsigned word = 0;
            int rb = 32 * w;
#pragma unroll
            for (int k = 0; k < 32; k++) {
                float si_ = ss[rb + k], ei_ = se_[rb + k], li_ = sl[rb + k];
                float interc = fmaxf(fminf(ej, ei_) - fmaxf(sj, si_), 0.0f);
                float uni = lj + li_ - interc;
                float um  = fmaxf(uni, 1e-8f);
                float diff = interc - 0.5f * um;
                bool sp;
                if (fabsf(diff) <= 1e-6f * um) sp = (interc / um) > 0.5f;
                else                           sp = diff > 0.0f;
                if (sp) word |= 1u << k;
            }
            if (w == g) word &= (1u << jl) - 1u;
            g_sup[(b * MAXG + w) * CAPB + j] = word;
        }
        return;
    }

    {   // ---- wide rank: per-CTA smem prefix of hist, 1 elem/thread ----
        __shared__ int spfx[NBUCK + 1];
        __shared__ int sps[256];
        int base_t = tid * 16;
        int local[16];
        {
            const int4* h4 = (const int4*)g_hist;
            int sum = 0;
#pragma unroll
            for (int k4 = 0; k4 < 4; k4++) {
                int4 v = h4[tid * 4 + k4];
                local[k4 * 4 + 0] = sum; sum += v.x;
                local[k4 * 4 + 1] = sum; sum += v.y;
                local[k4 * 4 + 2] = sum; sum += v.z;
                local[k4 * 4 + 3] = sum; sum += v.w;
            }
            sps[tid] = sum;
        }
        __syncthreads();
        if (tid < 32) {
            int vals[8], v = 0;
#pragma unroll
            for (int q = 0; q < 8; q++) { vals[q] = sps[tid * 8 + q]; v += vals[q]; }
            int inc = v;
#pragma unroll
            for (int ofs = 1; ofs < 32; ofs <<= 1) {
                int n = __shfl_up_sync(FULL, inc, ofs);
                if (tid >= ofs) inc += n;
            }
            int run = inc - v;
#pragma unroll
            for (int q = 0; q < 8; q++) { sps[tid * 8 + q] = run; run += vals[q]; }
        }
        __syncthreads();
        {
            int base = sps[tid];
#pragma unroll
            for (int k = 0; k < 16; k++) spfx[base_t + k] = base + local[k];
            if (tid == 255) spfx[NBUCK] = NN;
        }
        __syncthreads();

        int i  = (blk - MAXG * NB) * 256 + tid;
        float si = score[i];
        int bk = bucket_of(si);
        int lo = spfx[bk], hi = spfx[bk + 1];
        int r  = NN - hi;                      // strictly higher buckets
        int hcnt = hi - lo; if (hcnt > BCAP) hcnt = BCAP;
        for (int m = 0; m < hcnt; m++) {       // same bucket: exact tie-break
            int j = g_bucktab[bk * BCAP + m];
            float sj = score[j];
            r += (sj > si) || (sj == si && j < i);
        }
        g_rank[i] = r;
    }
}

// ---------------------------------------------------------------------------
// K3: per-batch — mask prefetch + ballot-fixpoint scan + writeback +
//     re-zero g_hist for next call.
// ---------------------------------------------------------------------------
__global__ void k3_kernel(float* __restrict__ out) {
    __shared__ __align__(16) unsigned ssup[MAXG * MAXC];
    __shared__ unsigned skeep[MAXG];
    int b   = blockIdx.x;
    int tid = threadIdx.x;

    if (tid < 128) g_hist[b * 128 + tid] = 0;   // self-clean for next call

    int ob  = g_off[b];
    int cnt = g_off[b + 1] - ob;
    if (cnt > MAXC) cnt = MAXC;
    if (cnt == 0) return;
    int nG = (cnt + 31) >> 5;

    int nwv = (32 * nG) >> 2;
    for (int w = 0; w < nG; w++) {
        const uint4* src = (const uint4*)&g_sup[(b * MAXG + w) * CAPB];
        uint4*       dst = (uint4*)&ssup[w * MAXC];
        for (int j = tid; j < nwv; j += 256) dst[j] = src[j];
    }
    __syncthreads();

    if (tid < 32) {
        int lane = tid;
        for (int g = 0; g < nG; g++) {
            int j = 32 * g + lane;
            bool valid = j < cnt;
            unsigned dead = 0;
            for (int w = 0; w < g; w++)
                dead |= valid ? (ssup[w * MAXC + j] & skeep[w]) : 0u;
            unsigned pend = valid ? ssup[g * MAXC + j] : 0u;
            bool alive0 = valid && (dead == 0u);
            unsigned M = __ballot_sync(FULL, alive0);
            for (;;) {                         // unique fixpoint = greedy
                unsigned Mn = __ballot_sync(FULL, alive0 && ((pend & M) == 0u));
                if (Mn == M) break;
                M = Mn;
            }
            skeep[g] = M;
            __syncwarp();
        }
    }
    __syncthreads();

    float* obds = out + (size_t)NB * NCLIP * 3;
    float* osc  = obds + 2 * NN;
    for (int t = tid; t < cnt; t += 256) {
        int r = g_rank[g_sidx[ob + t]];
        float f = ((skeep[t >> 5] >> (t & 31)) & 1u) ? 1.0f : 0.0f;
        obds[2 * r]     = g_ss[ob + t] * f;
        obds[2 * r + 1] = g_se[ob + t] * f;
        osc[r]          = g_ssc[ob + t] * f;
    }
}

// ---------------------------------------------------------------------------
extern "C" void kernel_launch(void* const* d_in, const int* in_sizes, int n_in,
                              void* d_out, int out_size) {
    const float* gt    = (const float*)d_in[0];
    const float* pred  = (const float*)d_in[1];
    const float* score = (const float*)d_in[2];
    const int*   bidx  = (const int*)d_in[3];
    float* out = (float*)d_out;

    k1_kernel<<<NB * QC + NB + NN / 256, 256>>>(gt, bidx, pred, score, out);
    k2_kernel<<<MAXG * NB + NN / 256, 256>>>(score);
    k3_kernel<<<NB, 256>>>(out);
}